// round 3
// baseline (speedup 1.0000x reference)
#include <cuda_runtime.h>
#include <math.h>

// Problem constants
#define B_  32
#define S_  2048
#define H_  1024
#define M_  (S_ * B_)      // 65536 rows of flattened key (s-major, b inner)
#define NB_ (H_ / 128)     // 8 n-tiles
#define SC_ 16             // s-chunks for the context split-K

// Device scratch (no allocations allowed)
__device__ float g_qw[B_ * H_];            // q@Wa + Wa_b + Ua_b          (128 KB)
__device__ float g_part[NB_ * M_];         // per-n-tile score partials   (2 MB)
__device__ float g_ctxp[SC_ * B_ * H_];    // context split-K partials    (2 MB)
__device__ float g_wfallback[B_ * S_];     // weights scratch if out_size only holds context

// ---------------------------------------------------------------------------
// Kernel 1: qw[b][n] = Wa_b[n] + Ua_b[n] + sum_k q[b][k] * Wa[k][n]
// grid (H/256, B), 256 threads
// ---------------------------------------------------------------------------
__global__ void qw_kernel(const float* __restrict__ q,
                          const float* __restrict__ Wa,
                          const float* __restrict__ Wab,
                          const float* __restrict__ Uab) {
    int b = blockIdx.y;
    int n = blockIdx.x * 256 + threadIdx.x;
    const float* qb = q + b * H_;
    float acc = Wab[n] + Uab[n];
#pragma unroll 4
    for (int k = 0; k < H_; k++)
        acc += qb[k] * Wa[k * H_ + n];
    g_qw[b * H_ + n] = acc;
}

// ---------------------------------------------------------------------------
// Kernel 2: fused energy GEMM.
// C[m][n] = key_flat[m][:] dot Ua[:][n]  (m = s*B + b)
// part[nb][m] = sum_{n in tile nb} va[n] * tanh(C[m][n] + qw[m%B][n])
// 128x128x16 tile, 256 threads, 8x8 per thread.
// grid (8 n-tiles, 512 m-tiles)  -> adjacent CTAs share the key tile via L2.
// ---------------------------------------------------------------------------
__global__ __launch_bounds__(256, 2)
void energy_kernel(const float* __restrict__ key,
                   const float* __restrict__ Ua,
                   const float* __restrict__ va) {
    __shared__ float As[16][132];   // transposed A tile, padded
    __shared__ float Bs[16][128];
    __shared__ float Qs[32][128];   // qw slice for this n-tile

    const int tid = threadIdx.x;
    const int tx  = tid & 15;       // n dim
    const int ty  = tid >> 4;       // m dim
    const int nb  = blockIdx.x;     // 0..7
    const int n0  = nb * 128;
    const int m0  = blockIdx.y * 128;

    // stage qw[0..31][n0..n0+127] into smem (4096 floats)
#pragma unroll
    for (int u = 0; u < 4; u++) {
        int lv  = tid + u * 256;          // float4 unit index, 0..1023
        int bb  = lv >> 5;                // 0..31
        int nn4 = (lv & 31) << 2;         // 0..124
        *(float4*)&Qs[bb][nn4] = *(const float4*)&g_qw[bb * H_ + n0 + nn4];
    }

    float va_f[8];
    *(float4*)&va_f[0] = *(const float4*)&va[n0 + tx * 8];
    *(float4*)&va_f[4] = *(const float4*)&va[n0 + tx * 8 + 4];

    float acc[8][8];
#pragma unroll
    for (int i = 0; i < 8; i++)
#pragma unroll
        for (int j = 0; j < 8; j++) acc[i][j] = 0.f;

    for (int kt = 0; kt < H_; kt += 16) {
        // A tile: 128 rows x 16 k, stored transposed As[k][m]
#pragma unroll
        for (int u = 0; u < 2; u++) {
            int t   = tid + u * 256;
            int row = t >> 2;             // 0..127
            int kc  = (t & 3) << 2;       // 0,4,8,12
            float4 v = *(const float4*)&key[(m0 + row) * H_ + kt + kc];
            As[kc + 0][row] = v.x;
            As[kc + 1][row] = v.y;
            As[kc + 2][row] = v.z;
            As[kc + 3][row] = v.w;
        }
        // B tile: 16 rows x 128 n
#pragma unroll
        for (int u = 0; u < 2; u++) {
            int t   = tid + u * 256;
            int row = t >> 5;             // 0..15
            int c4  = (t & 31) << 2;      // 0..124
            *(float4*)&Bs[row][c4] = *(const float4*)&Ua[(kt + row) * H_ + n0 + c4];
        }
        __syncthreads();

#pragma unroll
        for (int k = 0; k < 16; k++) {
            float a[8], bf[8];
            *(float4*)&a[0]  = *(float4*)&As[k][ty * 8];
            *(float4*)&a[4]  = *(float4*)&As[k][ty * 8 + 4];
            *(float4*)&bf[0] = *(float4*)&Bs[k][tx * 8];
            *(float4*)&bf[4] = *(float4*)&Bs[k][tx * 8 + 4];
#pragma unroll
            for (int i = 0; i < 8; i++)
#pragma unroll
                for (int j = 0; j < 8; j++)
                    acc[i][j] = fmaf(a[i], bf[j], acc[i][j]);
        }
        __syncthreads();
    }

    // Epilogue: tanh, weight by va, reduce the 128-wide n-tile per row.
#pragma unroll
    for (int i = 0; i < 8; i++) {
        int bb = (ty * 8 + i) & 31;       // m0 is a multiple of 128 -> of 32
        float rs = 0.f;
#pragma unroll
        for (int j = 0; j < 8; j++)
            rs += va_f[j] * tanhf(acc[i][j] + Qs[bb][tx * 8 + j]);
        // reduce across the 16 tx lanes (stay within 16-lane half-warp groups)
#pragma unroll
        for (int o = 8; o; o >>= 1)
            rs += __shfl_xor_sync(0xffffffffu, rs, o);
        if (tx == 0)
            g_part[nb * M_ + m0 + ty * 8 + i] = rs;
    }
}

// ---------------------------------------------------------------------------
// Kernel 3: softmax over S per batch. 32 blocks, 256 threads, 8 s per thread.
// Writes weights[b][s].  (va_b dropped: softmax is shift-invariant.)
// ---------------------------------------------------------------------------
__global__ void softmax_kernel(float* __restrict__ wout) {
    int b   = blockIdx.x;
    int tid = threadIdx.x;
    __shared__ float red[256];

    float sc[8];
#pragma unroll
    for (int u = 0; u < 8; u++) {
        int s = tid + u * 256;
        float v = 0.f;
#pragma unroll
        for (int nb = 0; nb < NB_; nb++)
            v += g_part[nb * M_ + s * B_ + b];
        sc[u] = v;
    }

    float mx = sc[0];
#pragma unroll
    for (int u = 1; u < 8; u++) mx = fmaxf(mx, sc[u]);
    red[tid] = mx;
    __syncthreads();
    for (int o = 128; o; o >>= 1) {
        if (tid < o) red[tid] = fmaxf(red[tid], red[tid + o]);
        __syncthreads();
    }
    mx = red[0];
    __syncthreads();

    float e[8];
    float sum = 0.f;
#pragma unroll
    for (int u = 0; u < 8; u++) {
        e[u] = expf(sc[u] - mx);
        sum += e[u];
    }
    red[tid] = sum;
    __syncthreads();
    for (int o = 128; o; o >>= 1) {
        if (tid < o) red[tid] += red[tid + o];
        __syncthreads();
    }
    float inv = 1.f / red[0];
#pragma unroll
    for (int u = 0; u < 8; u++)
        wout[b * S_ + tid + u * 256] = e[u] * inv;
}

// ---------------------------------------------------------------------------
// Kernel 4: context split-K.  grid (16 s-chunks, 32 b), 256 threads (4 h each).
// g_ctxp[sc][b][h] = sum_{s in chunk} w[b][s] * key[s][b][h]
// ---------------------------------------------------------------------------
__global__ void ctx_kernel(const float* __restrict__ key,
                           const float* __restrict__ w) {
    int schunk = blockIdx.x;
    int b      = blockIdx.y;
    int tid    = threadIdx.x;
    __shared__ float ws[128];
    if (tid < 128) ws[tid] = w[b * S_ + schunk * 128 + tid];
    __syncthreads();

    int h4 = tid * 4;
    const float* kb = key + ((schunk * 128) * B_ + b) * H_ + h4;
    float4 acc = make_float4(0.f, 0.f, 0.f, 0.f);
#pragma unroll 8
    for (int ss = 0; ss < 128; ss++) {
        float4 kv = *(const float4*)(kb + ss * B_ * H_);
        float wv  = ws[ss];
        acc.x = fmaf(wv, kv.x, acc.x);
        acc.y = fmaf(wv, kv.y, acc.y);
        acc.z = fmaf(wv, kv.z, acc.z);
        acc.w = fmaf(wv, kv.w, acc.w);
    }
    *(float4*)&g_ctxp[(schunk * B_ + b) * H_ + h4] = acc;
}

// Kernel 5: reduce the 16 context partials -> d_out[0 : B*H]
__global__ void ctx_reduce(float* __restrict__ out) {
    int i = blockIdx.x * 256 + threadIdx.x;    // 0..32767
    float v = 0.f;
#pragma unroll
    for (int sc = 0; sc < SC_; sc++)
        v += g_ctxp[sc * B_ * H_ + i];
    out[i] = v;
}

// ---------------------------------------------------------------------------
extern "C" void kernel_launch(void* const* d_in, const int* in_sizes, int n_in,
                              void* d_out, int out_size) {
    const float* query = (const float*)d_in[0];
    const float* key   = (const float*)d_in[1];
    const float* Wa_w  = (const float*)d_in[2];
    const float* Wa_b  = (const float*)d_in[3];
    const float* Ua_w  = (const float*)d_in[4];
    const float* Ua_b  = (const float*)d_in[5];
    const float* va_w  = (const float*)d_in[6];
    // d_in[7] = va_b : constant shift before softmax -> softmax-invariant, unused.

    float* out = (float*)d_out;

    // weights destination: after context if the output holds both, else scratch
    float* wdst;
    if (out_size >= B_ * H_ + B_ * S_) {
        wdst = out + B_ * H_;
    } else {
        void* p = nullptr;
        cudaGetSymbolAddress(&p, g_wfallback);
        wdst = (float*)p;
    }

    qw_kernel   <<<dim3(H_ / 256, B_), 256>>>(query, Wa_w, Wa_b, Ua_b);
    energy_kernel<<<dim3(NB_, M_ / 128), 256>>>(key, Ua_w, va_w);
    softmax_kernel<<<B_, 256>>>(wdst);
    ctx_kernel  <<<dim3(SC_, B_), 256>>>(key, wdst);
    ctx_reduce  <<<(B_ * H_) / 256, 256>>>(out);
}

// round 6
// speedup vs baseline: 1.7405x; 1.7405x over previous
#include <cuda_runtime.h>
#include <cuda_bf16.h>
#include <math.h>
#include <stdint.h>

// ---------------------------------------------------------------- constants
#define B_  32
#define S_  2048
#define H_  1024
#define M_  (S_ * B_)          // 65536 flattened key rows (m = s*B + b)
#define SC_ 32                 // context split-K chunks
#define SCHUNK_ (S_ / SC_)     // 64

#define NSTAGE_ 32             // K chunks of 32 elements
#define STAGEB_ 32768          // bytes per stage: A hi/lo 16K + B hi/lo 16K
#define QSOFF_  (3 * STAGEB_)  // 98304
#define SMEMTOT_ (QSOFF_ + 16384)   // 114688 (qw slice 128n x 32b floats)
#define NPLANES_ 32            // 8 n-blocks x 4 warp-cols

// ---------------------------------------------------------------- scratch
__device__ __nv_bfloat16 g_keyhi[(size_t)M_ * H_];   // 128 MB
__device__ __nv_bfloat16 g_keylo[(size_t)M_ * H_];   // 128 MB
__device__ __nv_bfloat16 g_UahiT[H_ * H_];           // Ua^T hi (rows n, cols k)
__device__ __nv_bfloat16 g_UaloT[H_ * H_];           // Ua^T lo
__device__ float g_qwT[H_ * B_];                     // qw transposed [n][b]
__device__ float g_part[(size_t)NPLANES_ * M_];      // [m][plane] score partials
__device__ float g_ctxp[SC_ * B_ * H_];
__device__ float g_wfallback[B_ * S_];

// ---------------------------------------------------------------- asm helpers
__device__ __forceinline__ uint32_t smem_u32(const void* p) {
    uint32_t a;
    asm("{ .reg .u64 t; cvta.to.shared.u64 t, %1; cvt.u32.u64 %0, t; }"
        : "=r"(a) : "l"(p));
    return a;
}

#define CP16(dst, src) \
    asm volatile("cp.async.cg.shared.global [%0], [%1], 16;" \
                 :: "r"(dst), "l"(src) : "memory")
#define CP_COMMIT()  asm volatile("cp.async.commit_group;" ::: "memory")
#define CP_WAIT1()   asm volatile("cp.async.wait_group 1;" ::: "memory")
#define CP_WAIT0()   asm volatile("cp.async.wait_group 0;" ::: "memory")

#define LDSM4(R0, R1, R2, R3, addr) \
    asm volatile("ldmatrix.sync.aligned.m8n8.x4.shared.b16 {%0,%1,%2,%3}, [%4];" \
                 : "=r"(R0), "=r"(R1), "=r"(R2), "=r"(R3) : "r"(addr))

#define MMA16816(C, A0, A1, A2, A3, B0, B1) \
    asm volatile("mma.sync.aligned.m16n8k16.row.col.f32.bf16.bf16.f32 " \
                 "{%0,%1,%2,%3}, {%4,%5,%6,%7}, {%8,%9}, {%0,%1,%2,%3};" \
                 : "+f"((C)[0]), "+f"((C)[1]), "+f"((C)[2]), "+f"((C)[3]) \
                 : "r"(A0), "r"(A1), "r"(A2), "r"(A3), "r"(B0), "r"(B1))

// ---------------------------------------------------------------- conversion
__global__ void conv_key_kernel(const float4* __restrict__ key4) {
    const size_t total = (size_t)M_ * H_ / 4;
    __nv_bfloat162* hp = (__nv_bfloat162*)g_keyhi;
    __nv_bfloat162* lp = (__nv_bfloat162*)g_keylo;
    for (size_t i = (size_t)blockIdx.x * blockDim.x + threadIdx.x; i < total;
         i += (size_t)gridDim.x * blockDim.x) {
        float4 v = key4[i];
        __nv_bfloat16 h0 = __float2bfloat16(v.x), h1 = __float2bfloat16(v.y);
        __nv_bfloat16 h2 = __float2bfloat16(v.z), h3 = __float2bfloat16(v.w);
        __nv_bfloat16 l0 = __float2bfloat16(v.x - __bfloat162float(h0));
        __nv_bfloat16 l1 = __float2bfloat16(v.y - __bfloat162float(h1));
        __nv_bfloat16 l2 = __float2bfloat16(v.z - __bfloat162float(h2));
        __nv_bfloat16 l3 = __float2bfloat16(v.w - __bfloat162float(h3));
        hp[2*i]   = __halves2bfloat162(h0, h1);
        hp[2*i+1] = __halves2bfloat162(h2, h3);
        lp[2*i]   = __halves2bfloat162(l0, l1);
        lp[2*i+1] = __halves2bfloat162(l2, l3);
    }
}

__global__ void conv_UaT_kernel(const float* __restrict__ Ua) {
    int idx = blockIdx.x * 256 + threadIdx.x;   // idx = n*H + k
    int n = idx >> 10, k = idx & 1023;
    float v = Ua[k * H_ + n];
    __nv_bfloat16 h = __float2bfloat16(v);
    g_UahiT[idx] = h;
    g_UaloT[idx] = __float2bfloat16(v - __bfloat162float(h));
}

// ---------------------------------------------------------------- qw^T
__global__ void qwT_kernel(const float* __restrict__ q,
                           const float* __restrict__ Wa,
                           const float* __restrict__ Wab,
                           const float* __restrict__ Uab) {
    int b = blockIdx.y;
    int n = blockIdx.x * 256 + threadIdx.x;
    const float* qb = q + b * H_;
    float acc = Wab[n] + Uab[n];
#pragma unroll 4
    for (int k = 0; k < H_; k++)
        acc = fmaf(qb[k], Wa[k * H_ + n], acc);
    g_qwT[n * B_ + b] = acc;
}

// ---------------------------------------------------------------- energy (HMMA)
// CTA 128x128 of C = key@Ua via 3-product bf16 split + fused tanh epilogue.
// Smem tile rows: 64B (32 bf16), 16B chunks swizzled chunk^=(row>>1)&3.
__global__ __launch_bounds__(256, 2)
void energy_mma(const float* __restrict__ va) {
    extern __shared__ __align__(1024) char smem[];
    const uint32_t sb = smem_u32(smem);
    const int tid  = threadIdx.x;
    const int lane = tid & 31, wid = tid >> 5;
    const int warp_m = wid >> 2, warp_n = wid & 3;
    const int n0g = blockIdx.x * 128;
    const int m0  = blockIdx.y * 128;

    // ---- stage loader (512 chunk-ids per variant; 2 per thread) ----
#define LOAD_STAGE(KT, BUF) do {                                              \
        const int kofs_ = (KT) * 32;                                          \
        const uint32_t st_ = sb + (uint32_t)(BUF) * STAGEB_;                  \
        _Pragma("unroll")                                                     \
        for (int u_ = 0; u_ < 2; u_++) {                                      \
            int id_ = tid + u_ * 256;                                         \
            int r_ = id_ >> 2, c_ = id_ & 3;                                  \
            uint32_t off_ = (uint32_t)(r_ * 64 + 16 * (c_ ^ ((r_ >> 1) & 3)));\
            size_t gA_ = (size_t)(m0 + r_) * H_ + kofs_ + c_ * 8;             \
            CP16(st_ + off_,         g_keyhi + gA_);                          \
            CP16(st_ + 8192 + off_,  g_keylo + gA_);                          \
            size_t gB_ = (size_t)(n0g + r_) * H_ + kofs_ + c_ * 8;            \
            CP16(st_ + 16384 + off_, g_UahiT + gB_);                          \
            CP16(st_ + 24576 + off_, g_UaloT + gB_);                          \
        }                                                                     \
    } while (0)

    // prologue: stages 0,1 + qw slice
    LOAD_STAGE(0, 0);
#pragma unroll
    for (int u = 0; u < 4; u++) {
        int idx = tid + u * 256;                 // float4 id 0..1023
        int nl = idx >> 3, b4 = (idx & 7) * 4;   // Qs[n][b]
        CP16(sb + QSOFF_ + (uint32_t)idx * 16,
             g_qwT + (size_t)(n0g + nl) * B_ + b4);
    }
    CP_COMMIT();
    LOAD_STAGE(1, 1);
    CP_COMMIT();

    // accumulators c[tm][nt][4]
    float c[4][4][4];
#pragma unroll
    for (int i = 0; i < 4; i++)
#pragma unroll
        for (int j = 0; j < 4; j++)
#pragma unroll
            for (int r = 0; r < 4; r++) c[i][j][r] = 0.f;

    const int lrow = lane & 7, jj = lane >> 3;
    const uint32_t swz = (uint32_t)((lrow >> 1) & 3);
    // lane-constant row offsets for ldmatrix
    const uint32_t arow = (uint32_t)((warp_m * 64 + 8 * (jj & 1) + lrow) * 64);
    const uint32_t brow = (uint32_t)((warp_n * 32 + 8 * (jj >> 1) + lrow) * 64);
    const uint32_t achunk = (uint32_t)(jj >> 1);   // k-half from matrix idx
    const uint32_t bchunk = (uint32_t)(jj & 1);

    for (int kt = 0; kt < NSTAGE_; kt++) {
        if (kt + 1 < NSTAGE_) CP_WAIT1(); else CP_WAIT0();
        __syncthreads();
        if (kt + 2 < NSTAGE_) { LOAD_STAGE(kt + 2, (kt + 2) % 3); CP_COMMIT(); }

        const uint32_t Ab = sb + (uint32_t)(kt % 3) * STAGEB_;
        const uint32_t Bb = Ab + 16384;

#pragma unroll
        for (int ks = 0; ks < 2; ks++) {
            uint32_t bh[4][2], bl[4][2];
#pragma unroll
            for (int nt16 = 0; nt16 < 2; nt16++) {
                uint32_t addr = Bb + brow + (uint32_t)(nt16 * 16 * 64)
                              + 16u * ((2u * ks + bchunk) ^ swz);
                LDSM4(bh[2*nt16][0], bh[2*nt16][1], bh[2*nt16+1][0], bh[2*nt16+1][1], addr);
                LDSM4(bl[2*nt16][0], bl[2*nt16][1], bl[2*nt16+1][0], bl[2*nt16+1][1], addr + 8192);
            }
#pragma unroll
            for (int tm = 0; tm < 4; tm++) {
                uint32_t addr = Ab + arow + (uint32_t)(tm * 16 * 64)
                              + 16u * ((2u * ks + achunk) ^ swz);
                uint32_t ah0, ah1, ah2, ah3, al0, al1, al2, al3;
                LDSM4(ah0, ah1, ah2, ah3, addr);
                LDSM4(al0, al1, al2, al3, addr + 8192);
#pragma unroll
                for (int nt = 0; nt < 4; nt++) {
                    MMA16816(c[tm][nt], ah0, ah1, ah2, ah3, bh[nt][0], bh[nt][1]);
                    MMA16816(c[tm][nt], ah0, ah1, ah2, ah3, bl[nt][0], bl[nt][1]);
                    MMA16816(c[tm][nt], al0, al1, al2, al3, bh[nt][0], bh[nt][1]);
                }
            }
        }
    }

    // ---- fused epilogue: score partials ----
    const int qlane = lane & 3, grp = lane >> 2;
    const float* Qs = (const float*)(smem + QSOFF_);

    float vreg[4][2];
#pragma unroll
    for (int nt = 0; nt < 4; nt++) {
        int n = n0g + warp_n * 32 + nt * 8 + 2 * qlane;
        vreg[nt][0] = __ldg(va + n);
        vreg[nt][1] = __ldg(va + n + 1);
    }

    float psum[4][2];
#pragma unroll
    for (int tm = 0; tm < 4; tm++) { psum[tm][0] = 0.f; psum[tm][1] = 0.f; }

#pragma unroll
    for (int tm = 0; tm < 4; tm++) {
        int bl_ = (tm * 16 + grp) & 31;
        int bh_ = (bl_ + 8) & 31;
#pragma unroll
        for (int nt = 0; nt < 4; nt++) {
            int nl = warp_n * 32 + nt * 8 + 2 * qlane;
            float q00 = Qs[nl * 32 + bl_],       q01 = Qs[(nl + 1) * 32 + bl_];
            float q10 = Qs[nl * 32 + bh_],       q11 = Qs[(nl + 1) * 32 + bh_];
            psum[tm][0] += vreg[nt][0] * tanhf(c[tm][nt][0] + q00)
                         + vreg[nt][1] * tanhf(c[tm][nt][1] + q01);
            psum[tm][1] += vreg[nt][0] * tanhf(c[tm][nt][2] + q10)
                         + vreg[nt][1] * tanhf(c[tm][nt][3] + q11);
        }
    }
    // reduce over the 4 quad lanes (they share the same m rows)
#pragma unroll
    for (int tm = 0; tm < 4; tm++)
#pragma unroll
        for (int h = 0; h < 2; h++) {
            psum[tm][h] += __shfl_xor_sync(0xffffffffu, psum[tm][h], 1);
            psum[tm][h] += __shfl_xor_sync(0xffffffffu, psum[tm][h], 2);
        }
    if (qlane == 0) {
        int plane = blockIdx.x * 4 + warp_n;
#pragma unroll
        for (int tm = 0; tm < 4; tm++)
#pragma unroll
            for (int h = 0; h < 2; h++) {
                int mg = m0 + warp_m * 64 + tm * 16 + h * 8 + grp;
                g_part[(size_t)mg * NPLANES_ + plane] = psum[tm][h];
            }
    }
#undef LOAD_STAGE
}

// ---------------------------------------------------------------- softmax
__global__ void softmax_kernel(float* __restrict__ wout) {
    int b = blockIdx.x, tid = threadIdx.x;
    __shared__ float red[256];
    float sc[8];
#pragma unroll
    for (int u = 0; u < 8; u++) {
        int s = tid + u * 256;
        const float4* pp = (const float4*)&g_part[(size_t)(s * B_ + b) * NPLANES_];
        float v = 0.f;
#pragma unroll
        for (int q = 0; q < 8; q++) {
            float4 t = pp[q];
            v += t.x + t.y + t.z + t.w;
        }
        sc[u] = v;
    }
    float mx = sc[0];
#pragma unroll
    for (int u = 1; u < 8; u++) mx = fmaxf(mx, sc[u]);
    red[tid] = mx; __syncthreads();
    for (int o = 128; o; o >>= 1) {
        if (tid < o) red[tid] = fmaxf(red[tid], red[tid + o]);
        __syncthreads();
    }
    mx = red[0]; __syncthreads();
    float e[8], sum = 0.f;
#pragma unroll
    for (int u = 0; u < 8; u++) { e[u] = expf(sc[u] - mx); sum += e[u]; }
    red[tid] = sum; __syncthreads();
    for (int o = 128; o; o >>= 1) {
        if (tid < o) red[tid] += red[tid + o];
        __syncthreads();
    }
    float inv = 1.f / red[0];
#pragma unroll
    for (int u = 0; u < 8; u++)
        wout[b * S_ + tid + u * 256] = e[u] * inv;
}

// ---------------------------------------------------------------- context
__global__ void ctx_kernel(const float* __restrict__ key,
                           const float* __restrict__ w) {
    int schunk = blockIdx.x, b = blockIdx.y, tid = threadIdx.x;
    __shared__ float ws[SCHUNK_];
    if (tid < SCHUNK_) ws[tid] = w[b * S_ + schunk * SCHUNK_ + tid];
    __syncthreads();
    int h4 = tid * 4;
    const float* kb = key + ((size_t)(schunk * SCHUNK_) * B_ + b) * H_ + h4;
    float4 acc = make_float4(0.f, 0.f, 0.f, 0.f);
#pragma unroll 8
    for (int ss = 0; ss < SCHUNK_; ss++) {
        float4 kv = *(const float4*)(kb + (size_t)ss * B_ * H_);
        float wv = ws[ss];
        acc.x = fmaf(wv, kv.x, acc.x);
        acc.y = fmaf(wv, kv.y, acc.y);
        acc.z = fmaf(wv, kv.z, acc.z);
        acc.w = fmaf(wv, kv.w, acc.w);
    }
    *(float4*)&g_ctxp[(size_t)(schunk * B_ + b) * H_ + h4] = acc;
}

__global__ void ctx_reduce(float* __restrict__ out) {
    int i = blockIdx.x * 256 + threadIdx.x;
    float v = 0.f;
#pragma unroll
    for (int sc = 0; sc < SC_; sc++)
        v += g_ctxp[(size_t)sc * B_ * H_ + i];
    out[i] = v;
}

// ---------------------------------------------------------------- launch
extern "C" void kernel_launch(void* const* d_in, const int* in_sizes, int n_in,
                              void* d_out, int out_size) {
    const float* query = (const float*)d_in[0];
    const float* key   = (const float*)d_in[1];
    const float* Wa_w  = (const float*)d_in[2];
    const float* Wa_b  = (const float*)d_in[3];
    const float* Ua_w  = (const float*)d_in[4];
    const float* Ua_b  = (const float*)d_in[5];
    const float* va_w  = (const float*)d_in[6];
    // d_in[7] = va_b : softmax-shift-invariant, unused.

    float* out = (float*)d_out;
    float* wdst;
    if (out_size >= B_ * H_ + B_ * S_) {
        wdst = out + B_ * H_;
    } else {
        void* p = nullptr;
        cudaGetSymbolAddress(&p, g_wfallback);
        wdst = (float*)p;
    }

    conv_key_kernel<<<16384, 256>>>((const float4*)key);
    conv_UaT_kernel<<<(H_ * H_) / 256, 256>>>(Ua_w);
    qwT_kernel<<<dim3(H_ / 256, B_), 256>>>(query, Wa_w, Wa_b, Ua_b);

    cudaFuncSetAttribute(energy_mma, cudaFuncAttributeMaxDynamicSharedMemorySize, SMEMTOT_);
    energy_mma<<<dim3(8, M_ / 128), 256, SMEMTOT_>>>(va_w);

    softmax_kernel<<<B_, 256>>>(wdst);
    ctx_kernel<<<dim3(SC_, B_), 256>>>(key, wdst);
    ctx_reduce<<<(B_ * H_) / 256, 256>>>(out);
}

// round 9
// speedup vs baseline: 3.4574x; 1.9864x over previous
#include <cuda_runtime.h>
#include <cuda_fp16.h>
#include <math.h>
#include <stdint.h>

// ---------------------------------------------------------------- constants
#define B_  32
#define S_  2048
#define H_  1024
#define M_  (S_ * B_)          // 65536 flattened key rows (m = s*B + b)
#define SC_ 32                 // context split-K chunks
#define SCHUNK_ (S_ / SC_)     // 64

#define NSTAGE_ 32             // K chunks of 32 elements
#define STAGEB_ 24576          // bytes/stage: A 8K + Bhi 8K + Blo 8K
#define QSOFF_  (3 * STAGEB_)  // 73728
#define SMEMTOT_ (QSOFF_ + 16384)   // 90112 (qw slice 128n x 32b floats)
#define NPLANES_ 32            // 8 n-blocks x 4 warp-cols

// ---------------------------------------------------------------- scratch
__device__ __half g_keyh[(size_t)M_ * H_];     // fp16(key), 128 MB
__device__ __half g_UahiT[H_ * H_];            // Ua^T hi (rows n, cols k)
__device__ __half g_UaloT[H_ * H_];            // Ua^T lo
__device__ float g_qwT[H_ * B_];               // qw transposed [n][b]
__device__ float g_part[(size_t)NPLANES_ * M_];// [m][plane] score partials
__device__ float g_ctxp[SC_ * B_ * H_];
__device__ float g_wfallback[B_ * S_];

// ---------------------------------------------------------------- asm helpers
__device__ __forceinline__ uint32_t smem_u32(const void* p) {
    uint32_t a;
    asm("{ .reg .u64 t; cvta.to.shared.u64 t, %1; cvt.u32.u64 %0, t; }"
        : "=r"(a) : "l"(p));
    return a;
}

#define CP16(dst, src) \
    asm volatile("cp.async.cg.shared.global [%0], [%1], 16;" \
                 :: "r"(dst), "l"(src) : "memory")
#define CP_COMMIT()  asm volatile("cp.async.commit_group;" ::: "memory")
#define CP_WAIT1()   asm volatile("cp.async.wait_group 1;" ::: "memory")
#define CP_WAIT0()   asm volatile("cp.async.wait_group 0;" ::: "memory")

#define LDSM4(R0, R1, R2, R3, addr) \
    asm volatile("ldmatrix.sync.aligned.m8n8.x4.shared.b16 {%0,%1,%2,%3}, [%4];" \
                 : "=r"(R0), "=r"(R1), "=r"(R2), "=r"(R3) : "r"(addr))

#define MMA16816(C, A0, A1, A2, A3, B0, B1) \
    asm volatile("mma.sync.aligned.m16n8k16.row.col.f32.f16.f16.f32 " \
                 "{%0,%1,%2,%3}, {%4,%5,%6,%7}, {%8,%9}, {%0,%1,%2,%3};" \
                 : "+f"((C)[0]), "+f"((C)[1]), "+f"((C)[2]), "+f"((C)[3]) \
                 : "r"(A0), "r"(A1), "r"(A2), "r"(A3), "r"(B0), "r"(B1))

// ---------------------------------------------------------------- conversion
__global__ void conv_key_kernel(const float4* __restrict__ key4) {
    const size_t total = (size_t)M_ * H_ / 4;
    __half2* hp = (__half2*)g_keyh;
    for (size_t i = (size_t)blockIdx.x * blockDim.x + threadIdx.x; i < total;
         i += (size_t)gridDim.x * blockDim.x) {
        float4 v = key4[i];
        hp[2*i]   = __floats2half2_rn(v.x, v.y);
        hp[2*i+1] = __floats2half2_rn(v.z, v.w);
    }
}

__global__ void conv_UaT_kernel(const float* __restrict__ Ua) {
    int idx = blockIdx.x * 256 + threadIdx.x;   // idx = n*H + k
    int n = idx >> 10, k = idx & 1023;
    float v = Ua[k * H_ + n];
    __half h = __float2half_rn(v);
    g_UahiT[idx] = h;
    g_UaloT[idx] = __float2half_rn(v - __half2float(h));
}

// ---------------------------------------------------------------- qw^T
__global__ void qwT_kernel(const float* __restrict__ q,
                           const float* __restrict__ Wa,
                           const float* __restrict__ Wab,
                           const float* __restrict__ Uab) {
    int b = blockIdx.y;
    int n = blockIdx.x * 256 + threadIdx.x;
    const float* qb = q + b * H_;
    float acc = Wab[n] + Uab[n];
#pragma unroll 4
    for (int k = 0; k < H_; k++)
        acc = fmaf(qb[k], Wa[k * H_ + n], acc);
    g_qwT[n * B_ + b] = acc;
}

// ---------------------------------------------------------------- energy (HMMA)
// CTA 128x128 of C = key@Ua, fp16 2-product split (A*Bhi + A*Blo), fused tanh.
// Smem tile rows: 64B (32 fp16), 16B chunks swizzled chunk^=(row>>1)&3.
__global__ __launch_bounds__(256, 2)
void energy_mma(const float* __restrict__ va) {
    extern __shared__ __align__(1024) char smem[];
    const uint32_t sb = smem_u32(smem);
    const int tid  = threadIdx.x;
    const int lane = tid & 31, wid = tid >> 5;
    const int warp_m = wid >> 2, warp_n = wid & 3;
    const int n0g = blockIdx.x * 128;
    const int m0  = blockIdx.y * 128;

    // ---- stage loader: 512 chunk-ids, 3 CP16 each (A, Bhi, Blo) ----
#define LOAD_STAGE(KT, BUF) do {                                              \
        const int kofs_ = (KT) * 32;                                          \
        const uint32_t st_ = sb + (uint32_t)(BUF) * STAGEB_;                  \
        _Pragma("unroll")                                                     \
        for (int u_ = 0; u_ < 2; u_++) {                                      \
            int id_ = tid + u_ * 256;                                         \
            int r_ = id_ >> 2, c_ = id_ & 3;                                  \
            uint32_t off_ = (uint32_t)(r_ * 64 + 16 * (c_ ^ ((r_ >> 1) & 3)));\
            size_t gA_ = (size_t)(m0 + r_) * H_ + kofs_ + c_ * 8;             \
            CP16(st_ + off_, g_keyh + gA_);                                   \
            size_t gB_ = (size_t)(n0g + r_) * H_ + kofs_ + c_ * 8;            \
            CP16(st_ + 8192 + off_,  g_UahiT + gB_);                          \
            CP16(st_ + 16384 + off_, g_UaloT + gB_);                          \
        }                                                                     \
    } while (0)

    // prologue: stages 0,1 + qw slice
    LOAD_STAGE(0, 0);
#pragma unroll
    for (int u = 0; u < 4; u++) {
        int idx = tid + u * 256;                 // float4 id 0..1023
        int nl = idx >> 3, b4 = (idx & 7) * 4;   // Qs[n][b]
        CP16(sb + QSOFF_ + (uint32_t)idx * 16,
             g_qwT + (size_t)(n0g + nl) * B_ + b4);
    }
    CP_COMMIT();
    LOAD_STAGE(1, 1);
    CP_COMMIT();

    // accumulators c[tm][nt][4]
    float c[4][4][4];
#pragma unroll
    for (int i = 0; i < 4; i++)
#pragma unroll
        for (int j = 0; j < 4; j++)
#pragma unroll
            for (int r = 0; r < 4; r++) c[i][j][r] = 0.f;

    const int lrow = lane & 7, jj = lane >> 3;
    const uint32_t swz = (uint32_t)((lrow >> 1) & 3);
    // lane-constant row offsets for ldmatrix
    const uint32_t arow = (uint32_t)((warp_m * 64 + 8 * (jj & 1) + lrow) * 64);
    const uint32_t brow = (uint32_t)((warp_n * 32 + 8 * (jj >> 1) + lrow) * 64);
    const uint32_t achunk = (uint32_t)(jj >> 1);   // k-half from matrix idx
    const uint32_t bchunk = (uint32_t)(jj & 1);

    for (int kt = 0; kt < NSTAGE_; kt++) {
        if (kt + 1 < NSTAGE_) CP_WAIT1(); else CP_WAIT0();
        __syncthreads();
        if (kt + 2 < NSTAGE_) { LOAD_STAGE(kt + 2, (kt + 2) % 3); CP_COMMIT(); }

        const uint32_t Ab = sb + (uint32_t)(kt % 3) * STAGEB_;
        const uint32_t Bb = Ab + 8192;

#pragma unroll
        for (int ks = 0; ks < 2; ks++) {
            uint32_t bh[4][2], bl[4][2];
#pragma unroll
            for (int nt16 = 0; nt16 < 2; nt16++) {
                uint32_t addr = Bb + brow + (uint32_t)(nt16 * 16 * 64)
                              + 16u * ((2u * ks + bchunk) ^ swz);
                LDSM4(bh[2*nt16][0], bh[2*nt16][1], bh[2*nt16+1][0], bh[2*nt16+1][1], addr);
                LDSM4(bl[2*nt16][0], bl[2*nt16][1], bl[2*nt16+1][0], bl[2*nt16+1][1], addr + 8192);
            }
#pragma unroll
            for (int tm = 0; tm < 4; tm++) {
                uint32_t addr = Ab + arow + (uint32_t)(tm * 16 * 64)
                              + 16u * ((2u * ks + achunk) ^ swz);
                uint32_t a0, a1, a2, a3;
                LDSM4(a0, a1, a2, a3, addr);
#pragma unroll
                for (int nt = 0; nt < 4; nt++) {
                    MMA16816(c[tm][nt], a0, a1, a2, a3, bh[nt][0], bh[nt][1]);
                    MMA16816(c[tm][nt], a0, a1, a2, a3, bl[nt][0], bl[nt][1]);
                }
            }
        }
    }

    // ---- fused epilogue: score partials ----
    const int qlane = lane & 3, grp = lane >> 2;
    const float* Qs = (const float*)(smem + QSOFF_);

    float vreg[4][2];
#pragma unroll
    for (int nt = 0; nt < 4; nt++) {
        int n = n0g + warp_n * 32 + nt * 8 + 2 * qlane;
        vreg[nt][0] = __ldg(va + n);
        vreg[nt][1] = __ldg(va + n + 1);
    }

    float psum[4][2];
#pragma unroll
    for (int tm = 0; tm < 4; tm++) { psum[tm][0] = 0.f; psum[tm][1] = 0.f; }

#pragma unroll
    for (int tm = 0; tm < 4; tm++) {
        int bl_ = (tm * 16 + grp) & 31;
        int bh_ = (bl_ + 8) & 31;
#pragma unroll
        for (int nt = 0; nt < 4; nt++) {
            int nl = warp_n * 32 + nt * 8 + 2 * qlane;
            float q00 = Qs[nl * 32 + bl_],       q01 = Qs[(nl + 1) * 32 + bl_];
            float q10 = Qs[nl * 32 + bh_],       q11 = Qs[(nl + 1) * 32 + bh_];
            psum[tm][0] += vreg[nt][0] * tanhf(c[tm][nt][0] + q00)
                         + vreg[nt][1] * tanhf(c[tm][nt][1] + q01);
            psum[tm][1] += vreg[nt][0] * tanhf(c[tm][nt][2] + q10)
                         + vreg[nt][1] * tanhf(c[tm][nt][3] + q11);
        }
    }
    // reduce over the 4 quad lanes (they share the same m rows)
#pragma unroll
    for (int tm = 0; tm < 4; tm++)
#pragma unroll
        for (int h = 0; h < 2; h++) {
            psum[tm][h] += __shfl_xor_sync(0xffffffffu, psum[tm][h], 1);
            psum[tm][h] += __shfl_xor_sync(0xffffffffu, psum[tm][h], 2);
        }
    if (qlane == 0) {
        int plane = blockIdx.x * 4 + warp_n;
#pragma unroll
        for (int tm = 0; tm < 4; tm++)
#pragma unroll
            for (int h = 0; h < 2; h++) {
                int mg = m0 + warp_m * 64 + tm * 16 + h * 8 + grp;
                g_part[(size_t)mg * NPLANES_ + plane] = psum[tm][h];
            }
    }
#undef LOAD_STAGE
}

// ---------------------------------------------------------------- softmax
__global__ void softmax_kernel(float* __restrict__ wout) {
    int b = blockIdx.x, tid = threadIdx.x;
    __shared__ float red[256];
    float sc[8];
#pragma unroll
    for (int u = 0; u < 8; u++) {
        int s = tid + u * 256;
        const float4* pp = (const float4*)&g_part[(size_t)(s * B_ + b) * NPLANES_];
        float v = 0.f;
#pragma unroll
        for (int q = 0; q < 8; q++) {
            float4 t = pp[q];
            v += t.x + t.y + t.z + t.w;
        }
        sc[u] = v;
    }
    float mx = sc[0];
#pragma unroll
    for (int u = 1; u < 8; u++) mx = fmaxf(mx, sc[u]);
    red[tid] = mx; __syncthreads();
    for (int o = 128; o; o >>= 1) {
        if (tid < o) red[tid] = fmaxf(red[tid], red[tid + o]);
        __syncthreads();
    }
    mx = red[0]; __syncthreads();
    float e[8], sum = 0.f;
#pragma unroll
    for (int u = 0; u < 8; u++) { e[u] = expf(sc[u] - mx); sum += e[u]; }
    red[tid] = sum; __syncthreads();
    for (int o = 128; o; o >>= 1) {
        if (tid < o) red[tid] += red[tid + o];
        __syncthreads();
    }
    float inv = 1.f / red[0];
#pragma unroll
    for (int u = 0; u < 8; u++)
        wout[b * S_ + tid + u * 256] = e[u] * inv;
}

// ---------------------------------------------------------------- context
__global__ void ctx_kernel(const float* __restrict__ key,
                           const float* __restrict__ w) {
    int schunk = blockIdx.x, b = blockIdx.y, tid = threadIdx.x;
    __shared__ float ws[SCHUNK_];
    if (tid < SCHUNK_) ws[tid] = w[b * S_ + schunk * SCHUNK_ + tid];
    __syncthreads();
    int h4 = tid * 4;
    const float* kb = key + ((size_t)(schunk * SCHUNK_) * B_ + b) * H_ + h4;
    float4 acc = make_float4(0.f, 0.f, 0.f, 0.f);
#pragma unroll 8
    for (int ss = 0; ss < SCHUNK_; ss++) {
        float4 kv = *(const float4*)(kb + (size_t)ss * B_ * H_);
        float wv = ws[ss];
        acc.x = fmaf(wv, kv.x, acc.x);
        acc.y = fmaf(wv, kv.y, acc.y);
        acc.z = fmaf(wv, kv.z, acc.z);
        acc.w = fmaf(wv, kv.w, acc.w);
    }
    *(float4*)&g_ctxp[(size_t)(schunk * B_ + b) * H_ + h4] = acc;
}

__global__ void ctx_reduce(float* __restrict__ out) {
    int i = blockIdx.x * 256 + threadIdx.x;
    float v = 0.f;
#pragma unroll
    for (int sc = 0; sc < SC_; sc++)
        v += g_ctxp[(size_t)sc * B_ * H_ + i];
    out[i] = v;
}

// ---------------------------------------------------------------- launch
extern "C" void kernel_launch(void* const* d_in, const int* in_sizes, int n_in,
                              void* d_out, int out_size) {
    const float* query = (const float*)d_in[0];
    const float* key   = (const float*)d_in[1];
    const float* Wa_w  = (const float*)d_in[2];
    const float* Wa_b  = (const float*)d_in[3];
    const float* Ua_w  = (const float*)d_in[4];
    const float* Ua_b  = (const float*)d_in[5];
    const float* va_w  = (const float*)d_in[6];
    // d_in[7] = va_b : softmax-shift-invariant, unused.

    float* out = (float*)d_out;
    float* wdst;
    if (out_size >= B_ * H_ + B_ * S_) {
        wdst = out + B_ * H_;
    } else {
        void* p = nullptr;
        cudaGetSymbolAddress(&p, g_wfallback);
        wdst = (float*)p;
    }

    conv_key_kernel<<<16384, 256>>>((const float4*)key);
    conv_UaT_kernel<<<(H_ * H_) / 256, 256>>>(Ua_w);
    qwT_kernel<<<dim3(H_ / 256, B_), 256>>>(query, Wa_w, Wa_b, Ua_b);

    cudaFuncSetAttribute(energy_mma, cudaFuncAttributeMaxDynamicSharedMemorySize, SMEMTOT_);
    energy_mma<<<dim3(8, M_ / 128), 256, SMEMTOT_>>>(va_w);

    softmax_kernel<<<B_, 256>>>(wdst);
    ctx_kernel<<<dim3(SC_, B_), 256>>>(key, wdst);
    ctx_reduce<<<(B_ * H_) / 256, 256>>>(out);
}

// round 10
// speedup vs baseline: 5.0919x; 1.4727x over previous
#include <cuda_runtime.h>
#include <cuda_fp16.h>
#include <math.h>
#include <stdint.h>

// ---------------------------------------------------------------- constants
#define B_  32
#define S_  2048
#define H_  1024
#define M_  (S_ * B_)          // 65536 flattened key rows (m = s*B + b)
#define SC_ 32                 // context split-K chunks
#define SCHUNK_ (S_ / SC_)     // 64

#define NSTAGE_ 32             // K chunks of 32 elements
#define STAGEB_ 16384          // bytes/stage: A 8K + B 8K
#define QSOFF_  (3 * STAGEB_)  // 49152
#define SMEMTOT_ (QSOFF_ + 16384)   // 65536 (qw slice 128n x 32b floats)
#define NPLANES_ 32            // 8 n-blocks x 4 warp-cols

// ---------------------------------------------------------------- scratch
__device__ __half g_keyh[(size_t)M_ * H_];     // fp16(key), 128 MB
__device__ __half g_UaT[H_ * H_];              // fp16(Ua^T) (rows n, cols k)
__device__ float g_qwT[H_ * B_];               // qw transposed [n][b]
__device__ float g_part[(size_t)NPLANES_ * M_];// [m][plane] score partials
__device__ float g_ctxp[SC_ * B_ * H_];
__device__ float g_wfallback[B_ * S_];

// ---------------------------------------------------------------- asm helpers
__device__ __forceinline__ uint32_t smem_u32(const void* p) {
    uint32_t a;
    asm("{ .reg .u64 t; cvta.to.shared.u64 t, %1; cvt.u32.u64 %0, t; }"
        : "=r"(a) : "l"(p));
    return a;
}

#define CP16(dst, src) \
    asm volatile("cp.async.cg.shared.global [%0], [%1], 16;" \
                 :: "r"(dst), "l"(src) : "memory")
#define CP_COMMIT()  asm volatile("cp.async.commit_group;" ::: "memory")
#define CP_WAIT1()   asm volatile("cp.async.wait_group 1;" ::: "memory")
#define CP_WAIT0()   asm volatile("cp.async.wait_group 0;" ::: "memory")

#define LDSM4(R0, R1, R2, R3, addr) \
    asm volatile("ldmatrix.sync.aligned.m8n8.x4.shared.b16 {%0,%1,%2,%3}, [%4];" \
                 : "=r"(R0), "=r"(R1), "=r"(R2), "=r"(R3) : "r"(addr))

#define MMA16816(C, A0, A1, A2, A3, B0, B1) \
    asm volatile("mma.sync.aligned.m16n8k16.row.col.f32.f16.f16.f32 " \
                 "{%0,%1,%2,%3}, {%4,%5,%6,%7}, {%8,%9}, {%0,%1,%2,%3};" \
                 : "+f"((C)[0]), "+f"((C)[1]), "+f"((C)[2]), "+f"((C)[3]) \
                 : "r"(A0), "r"(A1), "r"(A2), "r"(A3), "r"(B0), "r"(B1))

// ---------------------------------------------------------------- conversion
__global__ void conv_key_kernel(const float4* __restrict__ key4) {
    const size_t total = (size_t)M_ * H_ / 4;
    __half2* hp = (__half2*)g_keyh;
    for (size_t i = (size_t)blockIdx.x * blockDim.x + threadIdx.x; i < total;
         i += (size_t)gridDim.x * blockDim.x) {
        float4 v = key4[i];
        hp[2*i]   = __floats2half2_rn(v.x, v.y);
        hp[2*i+1] = __floats2half2_rn(v.z, v.w);
    }
}

__global__ void conv_UaT_kernel(const float* __restrict__ Ua) {
    int idx = blockIdx.x * 256 + threadIdx.x;   // idx = n*H + k
    int n = idx >> 10, k = idx & 1023;
    g_UaT[idx] = __float2half_rn(Ua[k * H_ + n]);
}

// ---------------------------------------------------------------- qw^T
__global__ void qwT_kernel(const float* __restrict__ q,
                           const float* __restrict__ Wa,
                           const float* __restrict__ Wab,
                           const float* __restrict__ Uab) {
    int b = blockIdx.y;
    int n = blockIdx.x * 256 + threadIdx.x;
    const float* qb = q + b * H_;
    float acc = Wab[n] + Uab[n];
#pragma unroll 4
    for (int k = 0; k < H_; k++)
        acc = fmaf(qb[k], Wa[k * H_ + n], acc);
    g_qwT[n * B_ + b] = acc;
}

// ---------------------------------------------------------------- energy (HMMA)
// CTA 128x128 of C = key@Ua, single fp16 product, fused tanh epilogue.
// Smem tile rows: 64B (32 fp16), 16B chunks swizzled chunk^=(row>>1)&3.
__global__ __launch_bounds__(256, 2)
void energy_mma(const float* __restrict__ va) {
    extern __shared__ __align__(1024) char smem[];
    const uint32_t sb = smem_u32(smem);
    const int tid  = threadIdx.x;
    const int lane = tid & 31, wid = tid >> 5;
    const int warp_m = wid >> 2, warp_n = wid & 3;
    const int n0g = blockIdx.x * 128;
    const int m0  = blockIdx.y * 128;

    // ---- stage loader: 512 chunk-ids, 2 CP16 each (A, B) ----
#define LOAD_STAGE(KT, BUF) do {                                              \
        const int kofs_ = (KT) * 32;                                          \
        const uint32_t st_ = sb + (uint32_t)(BUF) * STAGEB_;                  \
        _Pragma("unroll")                                                     \
        for (int u_ = 0; u_ < 2; u_++) {                                      \
            int id_ = tid + u_ * 256;                                         \
            int r_ = id_ >> 2, c_ = id_ & 3;                                  \
            uint32_t off_ = (uint32_t)(r_ * 64 + 16 * (c_ ^ ((r_ >> 1) & 3)));\
            size_t gA_ = (size_t)(m0 + r_) * H_ + kofs_ + c_ * 8;             \
            CP16(st_ + off_, g_keyh + gA_);                                   \
            size_t gB_ = (size_t)(n0g + r_) * H_ + kofs_ + c_ * 8;            \
            CP16(st_ + 8192 + off_, g_UaT + gB_);                             \
        }                                                                     \
    } while (0)

    // prologue: stages 0,1 + qw slice
    LOAD_STAGE(0, 0);
#pragma unroll
    for (int u = 0; u < 4; u++) {
        int idx = tid + u * 256;                 // float4 id 0..1023
        int nl = idx >> 3, b4 = (idx & 7) * 4;   // Qs[n][b]
        CP16(sb + QSOFF_ + (uint32_t)idx * 16,
             g_qwT + (size_t)(n0g + nl) * B_ + b4);
    }
    CP_COMMIT();
    LOAD_STAGE(1, 1);
    CP_COMMIT();

    // accumulators c[tm][nt][4]
    float c[4][4][4];
#pragma unroll
    for (int i = 0; i < 4; i++)
#pragma unroll
        for (int j = 0; j < 4; j++)
#pragma unroll
            for (int r = 0; r < 4; r++) c[i][j][r] = 0.f;

    const int lrow = lane & 7, jj = lane >> 3;
    const uint32_t swz = (uint32_t)((lrow >> 1) & 3);
    // lane-constant row offsets for ldmatrix
    const uint32_t arow = (uint32_t)((warp_m * 64 + 8 * (jj & 1) + lrow) * 64);
    const uint32_t brow = (uint32_t)((warp_n * 32 + 8 * (jj >> 1) + lrow) * 64);
    const uint32_t achunk = (uint32_t)(jj >> 1);   // k-half from matrix idx
    const uint32_t bchunk = (uint32_t)(jj & 1);

    for (int kt = 0; kt < NSTAGE_; kt++) {
        if (kt + 1 < NSTAGE_) CP_WAIT1(); else CP_WAIT0();
        __syncthreads();
        if (kt + 2 < NSTAGE_) { LOAD_STAGE(kt + 2, (kt + 2) % 3); CP_COMMIT(); }

        const uint32_t Ab = sb + (uint32_t)(kt % 3) * STAGEB_;
        const uint32_t Bb = Ab + 8192;

#pragma unroll
        for (int ks = 0; ks < 2; ks++) {
            uint32_t bh[4][2];
#pragma unroll
            for (int nt16 = 0; nt16 < 2; nt16++) {
                uint32_t addr = Bb + brow + (uint32_t)(nt16 * 16 * 64)
                              + 16u * ((2u * ks + bchunk) ^ swz);
                LDSM4(bh[2*nt16][0], bh[2*nt16][1], bh[2*nt16+1][0], bh[2*nt16+1][1], addr);
            }
#pragma unroll
            for (int tm = 0; tm < 4; tm++) {
                uint32_t addr = Ab + arow + (uint32_t)(tm * 16 * 64)
                              + 16u * ((2u * ks + achunk) ^ swz);
                uint32_t a0, a1, a2, a3;
                LDSM4(a0, a1, a2, a3, addr);
#pragma unroll
                for (int nt = 0; nt < 4; nt++)
                    MMA16816(c[tm][nt], a0, a1, a2, a3, bh[nt][0], bh[nt][1]);
            }
        }
    }

    // ---- fused epilogue: score partials ----
    const int qlane = lane & 3, grp = lane >> 2;
    const float* Qs = (const float*)(smem + QSOFF_);

    float vreg[4][2];
#pragma unroll
    for (int nt = 0; nt < 4; nt++) {
        int n = n0g + warp_n * 32 + nt * 8 + 2 * qlane;
        vreg[nt][0] = __ldg(va + n);
        vreg[nt][1] = __ldg(va + n + 1);
    }

    float psum[4][2];
#pragma unroll
    for (int tm = 0; tm < 4; tm++) { psum[tm][0] = 0.f; psum[tm][1] = 0.f; }

#pragma unroll
    for (int tm = 0; tm < 4; tm++) {
        int bl_ = (tm * 16 + grp) & 31;
        int bh_ = (bl_ + 8) & 31;
#pragma unroll
        for (int nt = 0; nt < 4; nt++) {
            int nl = warp_n * 32 + nt * 8 + 2 * qlane;
            float q00 = Qs[nl * 32 + bl_],       q01 = Qs[(nl + 1) * 32 + bl_];
            float q10 = Qs[nl * 32 + bh_],       q11 = Qs[(nl + 1) * 32 + bh_];
            psum[tm][0] += vreg[nt][0] * tanhf(c[tm][nt][0] + q00)
                         + vreg[nt][1] * tanhf(c[tm][nt][1] + q01);
            psum[tm][1] += vreg[nt][0] * tanhf(c[tm][nt][2] + q10)
                         + vreg[nt][1] * tanhf(c[tm][nt][3] + q11);
        }
    }
    // reduce over the 4 quad lanes (they share the same m rows)
#pragma unroll
    for (int tm = 0; tm < 4; tm++)
#pragma unroll
        for (int h = 0; h < 2; h++) {
            psum[tm][h] += __shfl_xor_sync(0xffffffffu, psum[tm][h], 1);
            psum[tm][h] += __shfl_xor_sync(0xffffffffu, psum[tm][h], 2);
        }
    if (qlane == 0) {
        int plane = blockIdx.x * 4 + warp_n;
#pragma unroll
        for (int tm = 0; tm < 4; tm++)
#pragma unroll
            for (int h = 0; h < 2; h++) {
                int mg = m0 + warp_m * 64 + tm * 16 + h * 8 + grp;
                g_part[(size_t)mg * NPLANES_ + plane] = psum[tm][h];
            }
    }
#undef LOAD_STAGE
}

// ---------------------------------------------------------------- softmax
__global__ void softmax_kernel(float* __restrict__ wout) {
    int b = blockIdx.x, tid = threadIdx.x;
    __shared__ float red[256];
    float sc[8];
#pragma unroll
    for (int u = 0; u < 8; u++) {
        int s = tid + u * 256;
        const float4* pp = (const float4*)&g_part[(size_t)(s * B_ + b) * NPLANES_];
        float v = 0.f;
#pragma unroll
        for (int q = 0; q < 8; q++) {
            float4 t = pp[q];
            v += t.x + t.y + t.z + t.w;
        }
        sc[u] = v;
    }
    float mx = sc[0];
#pragma unroll
    for (int u = 1; u < 8; u++) mx = fmaxf(mx, sc[u]);
    red[tid] = mx; __syncthreads();
    for (int o = 128; o; o >>= 1) {
        if (tid < o) red[tid] = fmaxf(red[tid], red[tid + o]);
        __syncthreads();
    }
    mx = red[0]; __syncthreads();
    float e[8], sum = 0.f;
#pragma unroll
    for (int u = 0; u < 8; u++) { e[u] = expf(sc[u] - mx); sum += e[u]; }
    red[tid] = sum; __syncthreads();
    for (int o = 128; o; o >>= 1) {
        if (tid < o) red[tid] += red[tid + o];
        __syncthreads();
    }
    float inv = 1.f / red[0];
#pragma unroll
    for (int u = 0; u < 8; u++)
        wout[b * S_ + tid + u * 256] = e[u] * inv;
}

// ---------------------------------------------------------------- context
// Reads fp16 key (half DRAM traffic vs fp32 original).
__global__ void ctx_kernel(const float* __restrict__ w) {
    int schunk = blockIdx.x, b = blockIdx.y, tid = threadIdx.x;
    __shared__ float ws[SCHUNK_];
    if (tid < SCHUNK_) ws[tid] = w[b * S_ + schunk * SCHUNK_ + tid];
    __syncthreads();
    int h4 = tid * 4;
    const __half* kb = g_keyh + ((size_t)(schunk * SCHUNK_) * B_ + b) * H_ + h4;
    float4 acc = make_float4(0.f, 0.f, 0.f, 0.f);
#pragma unroll 8
    for (int ss = 0; ss < SCHUNK_; ss++) {
        uint2 raw = *(const uint2*)(kb + (size_t)ss * B_ * H_);
        float2 f0 = __half22float2(*(const __half2*)&raw.x);
        float2 f1 = __half22float2(*(const __half2*)&raw.y);
        float wv = ws[ss];
        acc.x = fmaf(wv, f0.x, acc.x);
        acc.y = fmaf(wv, f0.y, acc.y);
        acc.z = fmaf(wv, f1.x, acc.z);
        acc.w = fmaf(wv, f1.y, acc.w);
    }
    *(float4*)&g_ctxp[(size_t)(schunk * B_ + b) * H_ + h4] = acc;
}

__global__ void ctx_reduce(float* __restrict__ out) {
    int i = blockIdx.x * 256 + threadIdx.x;
    float v = 0.f;
#pragma unroll
    for (int sc = 0; sc < SC_; sc++)
        v += g_ctxp[(size_t)sc * B_ * H_ + i];
    out[i] = v;
}

// ---------------------------------------------------------------- launch
extern "C" void kernel_launch(void* const* d_in, const int* in_sizes, int n_in,
                              void* d_out, int out_size) {
    const float* query = (const float*)d_in[0];
    const float* key   = (const float*)d_in[1];
    const float* Wa_w  = (const float*)d_in[2];
    const float* Wa_b  = (const float*)d_in[3];
    const float* Ua_w  = (const float*)d_in[4];
    const float* Ua_b  = (const float*)d_in[5];
    const float* va_w  = (const float*)d_in[6];
    // d_in[7] = va_b : softmax-shift-invariant, unused.

    float* out = (float*)d_out;
    float* wdst;
    if (out_size >= B_ * H_ + B_ * S_) {
        wdst = out + B_ * H_;
    } else {
        void* p = nullptr;
        cudaGetSymbolAddress(&p, g_wfallback);
        wdst = (float*)p;
    }

    conv_key_kernel<<<16384, 256>>>((const float4*)key);
    conv_UaT_kernel<<<(H_ * H_) / 256, 256>>>(Ua_w);
    qwT_kernel<<<dim3(H_ / 256, B_), 256>>>(query, Wa_w, Wa_b, Ua_b);

    cudaFuncSetAttribute(energy_mma, cudaFuncAttributeMaxDynamicSharedMemorySize, SMEMTOT_);
    energy_mma<<<dim3(8, M_ / 128), 256, SMEMTOT_>>>(va_w);

    softmax_kernel<<<B_, 256>>>(wdst);
    ctx_kernel<<<dim3(SC_, B_), 256>>>(wdst);
    ctx_reduce<<<(B_ * H_) / 256, 256>>>(out);
}

// round 11
// speedup vs baseline: 5.1844x; 1.0182x over previous
#include <cuda_runtime.h>
#include <cuda_fp16.h>
#include <math.h>
#include <stdint.h>

// ---------------------------------------------------------------- constants
#define B_  32
#define S_  2048
#define H_  1024
#define M_  (S_ * B_)          // 65536 flattened key rows (m = s*B + b)
#define SC_ 32                 // context split-K chunks
#define SCHUNK_ (S_ / SC_)     // 64

#define NSTAGE_ 16             // K chunks of 64 elements
#define STAGEB_ 32768          // bytes/stage: A 16K (2 subs) + B 16K (2 subs)
#define QSOFF_  (2 * STAGEB_)  // 65536
#define SMEMTOT_ (QSOFF_ + 16384)   // 81920 (qw slice 128n x 32b floats)
#define NPLANES_ 32            // 8 n-blocks x 4 warp-cols

// ---------------------------------------------------------------- scratch
__device__ __half g_keyh[(size_t)M_ * H_];     // fp16(key), 128 MB
__device__ __half g_UaT[H_ * H_];              // fp16(Ua^T) (rows n, cols k)
__device__ float g_qwT[H_ * B_];               // qw transposed [n][b]
__device__ float g_part[(size_t)NPLANES_ * M_];// [m][plane] score partials
__device__ float g_ctxp[SC_ * B_ * H_];
__device__ float g_wfallback[B_ * S_];

// ---------------------------------------------------------------- asm helpers
__device__ __forceinline__ uint32_t smem_u32(const void* p) {
    uint32_t a;
    asm("{ .reg .u64 t; cvta.to.shared.u64 t, %1; cvt.u32.u64 %0, t; }"
        : "=r"(a) : "l"(p));
    return a;
}

#define CP16(dst, src) \
    asm volatile("cp.async.cg.shared.global [%0], [%1], 16;" \
                 :: "r"(dst), "l"(src) : "memory")
#define CP_COMMIT()  asm volatile("cp.async.commit_group;" ::: "memory")
#define CP_WAIT0()   asm volatile("cp.async.wait_group 0;" ::: "memory")

#define LDSM4(R0, R1, R2, R3, addr) \
    asm volatile("ldmatrix.sync.aligned.m8n8.x4.shared.b16 {%0,%1,%2,%3}, [%4];" \
                 : "=r"(R0), "=r"(R1), "=r"(R2), "=r"(R3) : "r"(addr))

#define MMA16816(C, A0, A1, A2, A3, B0, B1) \
    asm volatile("mma.sync.aligned.m16n8k16.row.col.f32.f16.f16.f32 " \
                 "{%0,%1,%2,%3}, {%4,%5,%6,%7}, {%8,%9}, {%0,%1,%2,%3};" \
                 : "+f"((C)[0]), "+f"((C)[1]), "+f"((C)[2]), "+f"((C)[3]) \
                 : "r"(A0), "r"(A1), "r"(A2), "r"(A3), "r"(B0), "r"(B1))

// ---------------------------------------------------------------- conversion
__global__ void conv_key_kernel(const float4* __restrict__ key4) {
    const size_t total = (size_t)M_ * H_ / 4;
    __half2* hp = (__half2*)g_keyh;
    for (size_t i = (size_t)blockIdx.x * blockDim.x + threadIdx.x; i < total;
         i += (size_t)gridDim.x * blockDim.x) {
        float4 v = key4[i];
        hp[2*i]   = __floats2half2_rn(v.x, v.y);
        hp[2*i+1] = __floats2half2_rn(v.z, v.w);
    }
}

__global__ void conv_UaT_kernel(const float* __restrict__ Ua) {
    int idx = blockIdx.x * 256 + threadIdx.x;   // idx = n*H + k
    int n = idx >> 10, k = idx & 1023;
    g_UaT[idx] = __float2half_rn(Ua[k * H_ + n]);
}

// ---------------------------------------------------------------- qw^T
__global__ void qwT_kernel(const float* __restrict__ q,
                           const float* __restrict__ Wa,
                           const float* __restrict__ Wab,
                           const float* __restrict__ Uab) {
    int b = blockIdx.y;
    int n = blockIdx.x * 256 + threadIdx.x;
    const float* qb = q + b * H_;
    float acc = Wab[n] + Uab[n];
#pragma unroll 4
    for (int k = 0; k < H_; k++)
        acc = fmaf(qb[k], Wa[k * H_ + n], acc);
    g_qwT[n * B_ + b] = acc;
}

// ---------------------------------------------------------------- energy (HMMA)
// CTA 128x128 of C = key@Ua, single fp16 product, fused tanh epilogue.
// K staged in 64-element chunks (2 sub-chunks of 32), 2-stage ring.
// Smem tile rows: 64B (32 fp16), 16B chunks swizzled chunk^=(row>>1)&3.
__global__ __launch_bounds__(256, 2)
void energy_mma(const float* __restrict__ va) {
    extern __shared__ __align__(1024) char smem[];
    const uint32_t sb = smem_u32(smem);
    const int tid  = threadIdx.x;
    const int lane = tid & 31, wid = tid >> 5;
    const int warp_m = wid >> 2, warp_n = wid & 3;
    const int n0g = blockIdx.x * 128;
    const int m0  = blockIdx.y * 128;

    // ---- stage loader: 2 sub-chunks x 512 chunk-ids, 2 CP16 each ----
#define LOAD_STAGE(KT, BUF) do {                                              \
        const int kofs_ = (KT) * 64;                                          \
        const uint32_t st_ = sb + (uint32_t)(BUF) * STAGEB_;                  \
        _Pragma("unroll")                                                     \
        for (int s_ = 0; s_ < 2; s_++) {                                      \
            _Pragma("unroll")                                                 \
            for (int u_ = 0; u_ < 2; u_++) {                                  \
                int id_ = tid + u_ * 256;                                     \
                int r_ = id_ >> 2, c_ = id_ & 3;                              \
                uint32_t off_ = (uint32_t)(s_ * 8192 + r_ * 64                \
                               + 16 * (c_ ^ ((r_ >> 1) & 3)));                \
                size_t gA_ = (size_t)(m0 + r_) * H_ + kofs_ + s_ * 32 + c_ * 8;\
                CP16(st_ + off_, g_keyh + gA_);                               \
                size_t gB_ = (size_t)(n0g + r_) * H_ + kofs_ + s_ * 32 + c_ * 8;\
                CP16(st_ + 16384 + off_, g_UaT + gB_);                        \
            }                                                                 \
        }                                                                     \
    } while (0)

    // prologue: stage 0 + qw slice
    LOAD_STAGE(0, 0);
#pragma unroll
    for (int u = 0; u < 4; u++) {
        int idx = tid + u * 256;                 // float4 id 0..1023
        int nl = idx >> 3, b4 = (idx & 7) * 4;   // Qs[n][b]
        CP16(sb + QSOFF_ + (uint32_t)idx * 16,
             g_qwT + (size_t)(n0g + nl) * B_ + b4);
    }
    CP_COMMIT();

    // accumulators c[tm][nt][4]
    float c[4][4][4];
#pragma unroll
    for (int i = 0; i < 4; i++)
#pragma unroll
        for (int j = 0; j < 4; j++)
#pragma unroll
            for (int r = 0; r < 4; r++) c[i][j][r] = 0.f;

    const int lrow = lane & 7, jj = lane >> 3;
    const uint32_t swz = (uint32_t)((lrow >> 1) & 3);
    // lane-constant row offsets for ldmatrix
    const uint32_t arow = (uint32_t)((warp_m * 64 + 8 * (jj & 1) + lrow) * 64);
    const uint32_t brow = (uint32_t)((warp_n * 32 + 8 * (jj >> 1) + lrow) * 64);
    const uint32_t achunk = (uint32_t)(jj >> 1);   // k-half from matrix idx
    const uint32_t bchunk = (uint32_t)(jj & 1);

    for (int kt = 0; kt < NSTAGE_; kt++) {
        CP_WAIT0();              // only stage kt's group is outstanding here
        __syncthreads();
        if (kt + 1 < NSTAGE_) { LOAD_STAGE(kt + 1, (kt + 1) & 1); CP_COMMIT(); }

        const uint32_t stg = sb + (uint32_t)(kt & 1) * STAGEB_;

#pragma unroll
        for (int sub = 0; sub < 2; sub++) {
            const uint32_t Ab = stg + (uint32_t)(sub * 8192);
            const uint32_t Bb = stg + 16384u + (uint32_t)(sub * 8192);

#pragma unroll
            for (int ks = 0; ks < 2; ks++) {
                uint32_t bh[4][2];
#pragma unroll
                for (int nt16 = 0; nt16 < 2; nt16++) {
                    uint32_t addr = Bb + brow + (uint32_t)(nt16 * 16 * 64)
                                  + 16u * ((2u * ks + bchunk) ^ swz);
                    LDSM4(bh[2*nt16][0], bh[2*nt16][1], bh[2*nt16+1][0], bh[2*nt16+1][1], addr);
                }
#pragma unroll
                for (int tm = 0; tm < 4; tm++) {
                    uint32_t addr = Ab + arow + (uint32_t)(tm * 16 * 64)
                                  + 16u * ((2u * ks + achunk) ^ swz);
                    uint32_t a0, a1, a2, a3;
                    LDSM4(a0, a1, a2, a3, addr);
#pragma unroll
                    for (int nt = 0; nt < 4; nt++)
                        MMA16816(c[tm][nt], a0, a1, a2, a3, bh[nt][0], bh[nt][1]);
                }
            }
        }
        // barrier before next iteration overwrites the other buffer is the
        // CP_WAIT0+__syncthreads at loop top (all warps past compute of kt-1).
    }

    // ---- fused epilogue: score partials ----
    const int qlane = lane & 3, grp = lane >> 2;
    const float* Qs = (const float*)(smem + QSOFF_);

    float vreg[4][2];
#pragma unroll
    for (int nt = 0; nt < 4; nt++) {
        int n = n0g + warp_n * 32 + nt * 8 + 2 * qlane;
        vreg[nt][0] = __ldg(va + n);
        vreg[nt][1] = __ldg(va + n + 1);
    }

    float psum[4][2];
#pragma unroll
    for (int tm = 0; tm < 4; tm++) { psum[tm][0] = 0.f; psum[tm][1] = 0.f; }

#pragma unroll
    for (int tm = 0; tm < 4; tm++) {
        int bl_ = (tm * 16 + grp) & 31;
        int bh_ = (bl_ + 8) & 31;
#pragma unroll
        for (int nt = 0; nt < 4; nt++) {
            int nl = warp_n * 32 + nt * 8 + 2 * qlane;
            float q00 = Qs[nl * 32 + bl_],       q01 = Qs[(nl + 1) * 32 + bl_];
            float q10 = Qs[nl * 32 + bh_],       q11 = Qs[(nl + 1) * 32 + bh_];
            psum[tm][0] += vreg[nt][0] * tanhf(c[tm][nt][0] + q00)
                         + vreg[nt][1] * tanhf(c[tm][nt][1] + q01);
            psum[tm][1] += vreg[nt][0] * tanhf(c[tm][nt][2] + q10)
                         + vreg[nt][1] * tanhf(c[tm][nt][3] + q11);
        }
    }
    // reduce over the 4 quad lanes (they share the same m rows)
#pragma unroll
    for (int tm = 0; tm < 4; tm++)
#pragma unroll
        for (int h = 0; h < 2; h++) {
            psum[tm][h] += __shfl_xor_sync(0xffffffffu, psum[tm][h], 1);
            psum[tm][h] += __shfl_xor_sync(0xffffffffu, psum[tm][h], 2);
        }
    if (qlane == 0) {
        int plane = blockIdx.x * 4 + warp_n;
#pragma unroll
        for (int tm = 0; tm < 4; tm++)
#pragma unroll
            for (int h = 0; h < 2; h++) {
                int mg = m0 + warp_m * 64 + tm * 16 + h * 8 + grp;
                g_part[(size_t)mg * NPLANES_ + plane] = psum[tm][h];
            }
    }
#undef LOAD_STAGE
}

// ---------------------------------------------------------------- softmax
__global__ void softmax_kernel(float* __restrict__ wout) {
    int b = blockIdx.x, tid = threadIdx.x;
    __shared__ float red[256];
    float sc[8];
#pragma unroll
    for (int u = 0; u < 8; u++) {
        int s = tid + u * 256;
        const float4* pp = (const float4*)&g_part[(size_t)(s * B_ + b) * NPLANES_];
        float v = 0.f;
#pragma unroll
        for (int q = 0; q < 8; q++) {
            float4 t = pp[q];
            v += t.x + t.y + t.z + t.w;
        }
        sc[u] = v;
    }
    float mx = sc[0];
#pragma unroll
    for (int u = 1; u < 8; u++) mx = fmaxf(mx, sc[u]);
    red[tid] = mx; __syncthreads();
    for (int o = 128; o; o >>= 1) {
        if (tid < o) red[tid] = fmaxf(red[tid], red[tid + o]);
        __syncthreads();
    }
    mx = red[0]; __syncthreads();
    float e[8], sum = 0.f;
#pragma unroll
    for (int u = 0; u < 8; u++) { e[u] = expf(sc[u] - mx); sum += e[u]; }
    red[tid] = sum; __syncthreads();
    for (int o = 128; o; o >>= 1) {
        if (tid < o) red[tid] += red[tid + o];
        __syncthreads();
    }
    float inv = 1.f / red[0];
#pragma unroll
    for (int u = 0; u < 8; u++)
        wout[b * S_ + tid + u * 256] = e[u] * inv;
}

// ---------------------------------------------------------------- context
// Reads fp16 key (half DRAM traffic vs fp32 original).
__global__ void ctx_kernel(const float* __restrict__ w) {
    int schunk = blockIdx.x, b = blockIdx.y, tid = threadIdx.x;
    __shared__ float ws[SCHUNK_];
    if (tid < SCHUNK_) ws[tid] = w[b * S_ + schunk * SCHUNK_ + tid];
    __syncthreads();
    int h4 = tid * 4;
    const __half* kb = g_keyh + ((size_t)(schunk * SCHUNK_) * B_ + b) * H_ + h4;
    float4 acc = make_float4(0.f, 0.f, 0.f, 0.f);
#pragma unroll 8
    for (int ss = 0; ss < SCHUNK_; ss++) {
        uint2 raw = *(const uint2*)(kb + (size_t)ss * B_ * H_);
        float2 f0 = __half22float2(*(const __half2*)&raw.x);
        float2 f1 = __half22float2(*(const __half2*)&raw.y);
        float wv = ws[ss];
        acc.x = fmaf(wv, f0.x, acc.x);
        acc.y = fmaf(wv, f0.y, acc.y);
        acc.z = fmaf(wv, f1.x, acc.z);
        acc.w = fmaf(wv, f1.y, acc.w);
    }
    *(float4*)&g_ctxp[(size_t)(schunk * B_ + b) * H_ + h4] = acc;
}

__global__ void ctx_reduce(float* __restrict__ out) {
    int i = blockIdx.x * 256 + threadIdx.x;
    float v = 0.f;
#pragma unroll
    for (int sc = 0; sc < SC_; sc++)
        v += g_ctxp[(size_t)sc * B_ * H_ + i];
    out[i] = v;
}

// ---------------------------------------------------------------- launch
extern "C" void kernel_launch(void* const* d_in, const int* in_sizes, int n_in,
                              void* d_out, int out_size) {
    const float* query = (const float*)d_in[0];
    const float* key   = (const float*)d_in[1];
    const float* Wa_w  = (const float*)d_in[2];
    const float* Wa_b  = (const float*)d_in[3];
    const float* Ua_w  = (const float*)d_in[4];
    const float* Ua_b  = (const float*)d_in[5];
    const float* va_w  = (const float*)d_in[6];
    // d_in[7] = va_b : softmax-shift-invariant, unused.

    float* out = (float*)d_out;
    float* wdst;
    if (out_size >= B_ * H_ + B_ * S_) {
        wdst = out + B_ * H_;
    } else {
        void* p = nullptr;
        cudaGetSymbolAddress(&p, g_wfallback);
        wdst = (float*)p;
    }

    conv_key_kernel<<<16384, 256>>>((const float4*)key);
    conv_UaT_kernel<<<(H_ * H_) / 256, 256>>>(Ua_w);
    qwT_kernel<<<dim3(H_ / 256, B_), 256>>>(query, Wa_w, Wa_b, Ua_b);

    cudaFuncSetAttribute(energy_mma, cudaFuncAttributeMaxDynamicSharedMemorySize, SMEMTOT_);
    energy_mma<<<dim3(8, M_ / 128), 256, SMEMTOT_>>>(va_w);

    softmax_kernel<<<B_, 256>>>(wdst);
    ctx_kernel<<<dim3(SC_, B_), 256>>>(wdst);
    ctx_reduce<<<(B_ * H_) / 256, 256>>>(out);
}